// round 9
// baseline (speedup 1.0000x reference)
#include <cuda_runtime.h>
#include <cuda_bf16.h>
#include <cstdint>

// Embedding gather, hybrid: per-lane LDG.128 reads (L2-hit friendly, MLP=8)
// -> SMEM -> ONE contiguous 32KB cp.async.bulk store per CTA.
// out rows of a CTA are contiguous, so the write side becomes a single
// maximal bulk burst with zero per-lane STG issue cost.

#define DIM4     256   // float4s per row
#define THREADS  256
#define ROWS     8     // rows per CTA -> 32KB contiguous output burst
#define ROW_BYTES 4096

__device__ __forceinline__ uint32_t smem_u32(const void* p) {
    return (uint32_t)__cvta_generic_to_shared(p);
}

__global__ void __launch_bounds__(THREADS)
embedding_hybrid_kernel(const int* __restrict__ token_ids,
                        const float4* __restrict__ e,    // [32000, DIM4]
                        char* __restrict__ out,          // [n_tok, 4096 B]
                        int n_tok)
{
    __shared__ alignas(128) float4 buf[ROWS * DIM4];     // 32 KB

    const int row0 = blockIdx.x * ROWS;
    const int c    = threadIdx.x;
    const int nr   = (n_tok - row0 < ROWS) ? (n_tok - row0) : ROWS;

    // 1) Batched index loads (broadcast sectors).
    int toks[ROWS];
#pragma unroll
    for (int r = 0; r < ROWS; r++)
        toks[r] = (r < nr) ? __ldg(&token_ids[row0 + r]) : 0;

    // 2) Front-issue all independent row loads (MLP=8 per thread).
    float4 v[ROWS];
#pragma unroll
    for (int r = 0; r < ROWS; r++)
        v[r] = __ldg(&e[(long long)toks[r] * DIM4 + c]);

    // 3) Stage into SMEM (conflict-free: consecutive lanes -> consecutive banks).
#pragma unroll
    for (int r = 0; r < ROWS; r++)
        buf[r * DIM4 + c] = v[r];

    __syncthreads();

    // 4) One contiguous bulk store for the whole CTA's output slab.
    if (threadIdx.x == 0) {
        asm volatile("fence.proxy.async.shared::cta;" ::: "memory");
        const uint64_t dst = (uint64_t)__cvta_generic_to_global(out) +
                             (uint64_t)row0 * ROW_BYTES;
        const uint32_t src = smem_u32(buf);
        const uint32_t bytes = (uint32_t)nr * ROW_BYTES;
        asm volatile(
            "cp.async.bulk.global.shared::cta.bulk_group [%0], [%1], %2;"
            :: "l"(dst), "r"(src), "r"(bytes) : "memory");
        asm volatile("cp.async.bulk.commit_group;" ::: "memory");
        asm volatile("cp.async.bulk.wait_group 0;" ::: "memory");
    }
}

extern "C" void kernel_launch(void* const* d_in, const int* in_sizes, int n_in,
                              void* d_out, int out_size)
{
    // Robust to input ordering: token_ids is the small int32 buffer,
    // e is the large fp32 table.
    const int* token_ids;
    const float4* e;
    if (n_in >= 2 && in_sizes[0] > in_sizes[1]) {
        e         = (const float4*)d_in[0];
        token_ids = (const int*)d_in[1];
    } else {
        token_ids = (const int*)d_in[0];
        e         = (const float4*)d_in[1];
    }
    char* out = (char*)d_out;

    const int n_tok = out_size / (DIM4 * 4);            // 8192
    const int grid  = (n_tok + ROWS - 1) / ROWS;        // 1024
    embedding_hybrid_kernel<<<grid, THREADS>>>(token_ids, e, out, n_tok);
}

// round 10
// speedup vs baseline: 1.0178x; 1.0178x over previous
#include <cuda_runtime.h>
#include <cuda_bf16.h>

// Embedding gather: out[t,:] = e[token_ids[t],:]
// R6 structure (MLP=8 batched row loads) + STREAMING stores (__stcs -> STG.CS)
// so output lines don't write-allocate in L2 / evict the resident table.

#define DIM4     256   // float4s per row
#define THREADS  512   // 2 float4 columns per thread
#define ROWS     8     // rows per CTA

__global__ void __launch_bounds__(THREADS)
embedding_stream_kernel(const int* __restrict__ token_ids,
                        const float4* __restrict__ e,    // [32000, DIM4]
                        float4* __restrict__ out,        // [n_tok, DIM4]
                        int n_tok)
{
    const int row0 = blockIdx.x * ROWS;
    // Each thread handles one float4 column in one half-row pair:
    // threads 0..255 -> columns 0..255 of even work, 256..511 -> same cols,
    // we simply split ROWS across the two halves to keep full coalescing.
    const int half = threadIdx.x >> 8;          // 0 or 1
    const int c    = threadIdx.x & 255;         // float4 column
    const int rbeg = half * (ROWS / 2);         // rows 0..3 or 4..7

    // 1) Batched index loads (uniform -> broadcast sectors).
    int toks[ROWS / 2];
#pragma unroll
    for (int i = 0; i < ROWS / 2; i++) {
        int row = row0 + rbeg + i;
        toks[i] = (row < n_tok) ? __ldg(&token_ids[row]) : 0;
    }

    // 2) Front-issue all independent row loads (MLP=4 per thread, x512 threads).
    float4 v[ROWS / 2];
#pragma unroll
    for (int i = 0; i < ROWS / 2; i++)
        v[i] = __ldg(&e[(long long)toks[i] * DIM4 + c]);

    // 3) Streaming stores: evict-first, don't pollute L2.
#pragma unroll
    for (int i = 0; i < ROWS / 2; i++) {
        int row = row0 + rbeg + i;
        if (row < n_tok)
            __stcs(&out[(long long)row * DIM4 + c], v[i]);
    }
}

extern "C" void kernel_launch(void* const* d_in, const int* in_sizes, int n_in,
                              void* d_out, int out_size)
{
    // Robust to input ordering: token_ids is the small int32 buffer,
    // e is the large fp32 table.
    const int* token_ids;
    const float4* e;
    if (n_in >= 2 && in_sizes[0] > in_sizes[1]) {
        e         = (const float4*)d_in[0];
        token_ids = (const int*)d_in[1];
    } else {
        token_ids = (const int*)d_in[0];
        e         = (const float4*)d_in[1];
    }
    float4* out = (float4*)d_out;

    const int n_tok = out_size / (DIM4 * 4);            // 8192
    const int grid  = (n_tok + ROWS - 1) / ROWS;        // 1024
    embedding_stream_kernel<<<grid, THREADS>>>(token_ids, e, out, n_tok);
}